// round 1
// baseline (speedup 1.0000x reference)
#include <cuda_runtime.h>
#include <cuda_bf16.h>

// Problem constants (shapes fixed by the dataset)
#define NMAX 50048        // >= 50000, padded
#define EMAX 800000
#define DIM  128
#define NHEADS 8
#define HDIM 16

// ---------------- scratch (device globals; no allocation allowed) -------------
__device__ float    g_q[NMAX * DIM];
__device__ float    g_k[NMAX * DIM];
__device__ float    g_v[NMAX * DIM];
__device__ float    g_agg[NMAX * DIM];
__device__ float    g_scores[(size_t)EMAX * NHEADS];
__device__ unsigned g_mkey[NMAX * NHEADS];
__device__ float    g_denom[NMAX * NHEADS];

// Monotonic float<->uint encoding so unsigned atomicMax == float max.
__device__ __forceinline__ unsigned enc_f(float f) {
    unsigned u = __float_as_uint(f);
    return (u & 0x80000000u) ? ~u : (u | 0x80000000u);
}
__device__ __forceinline__ float dec_f(unsigned k) {
    return __uint_as_float((k & 0x80000000u) ? (k ^ 0x80000000u) : ~k);
}

// ---------------- K0: init scratch --------------------------------------------
__global__ void init_kernel(int n) {
    int total = n * DIM;
    int nh = n * NHEADS;
    for (int i = blockIdx.x * blockDim.x + threadIdx.x; i < total;
         i += gridDim.x * blockDim.x) {
        g_agg[i] = 0.0f;
        if (i < nh) { g_mkey[i] = 0u; g_denom[i] = 0.0f; }
    }
}

// ---------------- K1: fused QKV projection ------------------------------------
// out[m][i][j] = b_m[j] + sum_d h[i][d] * W_m[j][d],  m in {q,k,v}
// 768 threads = 2 row-groups x 384 column-threads (384 = 3 matrices x 128 cols).
// All 3 weight matrices live in smem in a float4-friendly, bank-conflict-free
// padded layout: float4 index = d4 * 385 + t   (t = m*128 + j)
#define QKV_NT 384
#define QKV_W4STRIDE (QKV_NT + 1)                 // 385 float4s per d4 slab
#define QKV_WFLOATS  (32 * QKV_W4STRIDE * 4)      // 49280 floats
#define QKV_SMEM ((QKV_WFLOATS + 2 * 16 * DIM) * 4)

__global__ __launch_bounds__(768, 1)
void qkv_kernel(const float* __restrict__ h,
                const float* __restrict__ Wq, const float* __restrict__ bq,
                const float* __restrict__ Wk, const float* __restrict__ bk,
                const float* __restrict__ Wv, const float* __restrict__ bv,
                int n) {
    extern __shared__ float smem[];
    float* Wsf = smem;                     // QKV_WFLOATS
    float* hs  = smem + QKV_WFLOATS;       // 2 groups x 16 rows x 128

    int tid = threadIdx.x;

    // Load 3 x 128 x 128 weights, coalesced global reads, conflict-free STS.
    for (int u = tid; u < 3 * DIM * DIM; u += blockDim.x) {
        int m = u >> 14;
        int rem = u & 16383;           // j*128 + d
        int j = rem >> 7;
        int d = rem & 127;
        int t = m * DIM + j;
        const float* wp = (m == 0) ? Wq : (m == 1) ? Wk : Wv;
        Wsf[(d >> 2) * (QKV_W4STRIDE * 4) + t * 4 + (d & 3)] = wp[rem];
    }

    int grp = tid / QKV_NT;            // 0..1
    int t   = tid % QKV_NT;
    int m   = t >> 7;
    int j   = t & 127;
    float bias = (m == 0) ? bq[j] : (m == 1) ? bk[j] : bv[j];
    float* outm = (m == 0) ? g_q : (m == 1) ? g_k : g_v;
    float* hsg = hs + grp * 16 * DIM;
    __syncthreads();

    const float4* Ws4 = (const float4*)Wsf;

    for (int b0 = blockIdx.x * 32; b0 < n; b0 += gridDim.x * 32) {
        int r0 = b0 + grp * 16;
        int nr = n - r0;
        nr = nr < 0 ? 0 : (nr > 16 ? 16 : nr);

        for (int u = t; u < nr * DIM; u += QKV_NT)
            hsg[u] = h[(size_t)r0 * DIM + u];
        __syncthreads();

        float acc[16];
        #pragma unroll
        for (int r = 0; r < 16; r++) acc[r] = 0.0f;

        const float4* hs4 = (const float4*)hsg;
        #pragma unroll 8
        for (int d4 = 0; d4 < 32; d4++) {
            float4 w4 = Ws4[d4 * QKV_W4STRIDE + t];
            #pragma unroll
            for (int r = 0; r < 16; r++) {
                float4 h4 = hs4[r * 32 + d4];
                acc[r] = fmaf(h4.x, w4.x,
                         fmaf(h4.y, w4.y,
                         fmaf(h4.z, w4.z,
                         fmaf(h4.w, w4.w, acc[r]))));
            }
        }
        __syncthreads();

        for (int r = 0; r < nr; r++)
            outm[(size_t)(r0 + r) * DIM + j] = acc[r] + bias;
    }
}

// ---------------- K2: per-edge scores + segment max ---------------------------
// One warp per edge. Lane l covers dims 4l..4l+3; head = l>>2.
__global__ void scores_kernel(const int* __restrict__ src,
                              const int* __restrict__ dst, int E) {
    int w = (blockIdx.x * blockDim.x + threadIdx.x) >> 5;
    int l = threadIdx.x & 31;
    if (w >= E) return;
    int s = src[w];
    int d = dst[w];
    float4 q4 = ((const float4*)g_q)[(size_t)s * 32 + l];
    float4 k4 = ((const float4*)g_k)[(size_t)d * 32 + l];
    float p = q4.x * k4.x + q4.y * k4.y + q4.z * k4.z + q4.w * k4.w;
    p += __shfl_xor_sync(0xffffffffu, p, 1);
    p += __shfl_xor_sync(0xffffffffu, p, 2);
    p *= 0.25f;                                  // 1/sqrt(16)
    if ((l & 3) == 0) {
        int hh = l >> 2;
        g_scores[(size_t)w * NHEADS + hh] = p;
        atomicMax(&g_mkey[(size_t)d * NHEADS + hh], enc_f(p));
    }
}

// ---------------- K3: exp + weighted aggregation (unnormalized) ---------------
__global__ void agg_kernel(const int* __restrict__ src,
                           const int* __restrict__ dst, int E) {
    int w = (blockIdx.x * blockDim.x + threadIdx.x) >> 5;
    int l = threadIdx.x & 31;
    if (w >= E) return;
    int s = src[w];
    int d = dst[w];
    int hh = l >> 2;
    float sc = g_scores[(size_t)w * NHEADS + hh];
    float mx = dec_f(g_mkey[(size_t)d * NHEADS + hh]);
    float we = __expf(sc - mx);
    float4 v4 = ((const float4*)g_v)[(size_t)s * 32 + l];
    float* dp = &g_agg[(size_t)d * DIM + l * 4];
    asm volatile("red.global.add.v4.f32 [%0], {%1, %2, %3, %4};"
                 :: "l"(dp), "f"(we * v4.x), "f"(we * v4.y),
                    "f"(we * v4.z), "f"(we * v4.w)
                 : "memory");
    if ((l & 3) == 0)
        atomicAdd(&g_denom[(size_t)d * NHEADS + hh], we);
}

// ---------------- K4: normalize agg in place ----------------------------------
__global__ void norm_kernel(int n) {
    int total = n * DIM;
    for (int i = blockIdx.x * blockDim.x + threadIdx.x; i < total;
         i += gridDim.x * blockDim.x) {
        float dn = g_denom[(i >> 7) * NHEADS + ((i & 127) >> 4)];
        float v = g_agg[i];
        g_agg[i] = (dn > 0.0f) ? (v / dn) : 0.0f;
    }
}

// ---------------- K5: output projection ---------------------------------------
// out[i][j] = bo[j] + sum_d agg[i][d] * Wo[j][d]
// 512 threads = 4 row-groups x 128 column-threads.
#define OUT_NT 128
#define OUT_W4STRIDE (OUT_NT + 1)                 // 129 float4s per d4 slab
#define OUT_WFLOATS  (32 * OUT_W4STRIDE * 4)      // 16512 floats
#define OUT_SMEM ((OUT_WFLOATS + 4 * 16 * DIM) * 4)

__global__ __launch_bounds__(512, 2)
void outproj_kernel(const float* __restrict__ W, const float* __restrict__ b,
                    float* __restrict__ out, int n) {
    extern __shared__ float smem[];
    float* Wsf = smem;
    float* hs  = smem + OUT_WFLOATS;

    int tid = threadIdx.x;
    for (int u = tid; u < DIM * DIM; u += blockDim.x) {
        int j = u >> 7;
        int d = u & 127;
        Wsf[(d >> 2) * (OUT_W4STRIDE * 4) + j * 4 + (d & 3)] = W[u];
    }

    int grp = tid >> 7;
    int t   = tid & 127;
    float bias = b[t];
    float* hsg = hs + grp * 16 * DIM;
    __syncthreads();

    const float4* Ws4 = (const float4*)Wsf;

    for (int b0 = blockIdx.x * 64; b0 < n; b0 += gridDim.x * 64) {
        int r0 = b0 + grp * 16;
        int nr = n - r0;
        nr = nr < 0 ? 0 : (nr > 16 ? 16 : nr);

        for (int u = t; u < nr * DIM; u += OUT_NT)
            hsg[u] = g_agg[(size_t)r0 * DIM + u];
        __syncthreads();

        float acc[16];
        #pragma unroll
        for (int r = 0; r < 16; r++) acc[r] = 0.0f;

        const float4* hs4 = (const float4*)hsg;
        #pragma unroll 8
        for (int d4 = 0; d4 < 32; d4++) {
            float4 w4 = Ws4[d4 * OUT_W4STRIDE + t];
            #pragma unroll
            for (int r = 0; r < 16; r++) {
                float4 h4 = hs4[r * 32 + d4];
                acc[r] = fmaf(h4.x, w4.x,
                         fmaf(h4.y, w4.y,
                         fmaf(h4.z, w4.z,
                         fmaf(h4.w, w4.w, acc[r]))));
            }
        }
        __syncthreads();

        for (int r = 0; r < nr; r++)
            out[(size_t)(r0 + r) * DIM + t] = acc[r] + bias;
    }
}

// ---------------- launch -------------------------------------------------------
extern "C" void kernel_launch(void* const* d_in, const int* in_sizes, int n_in,
                              void* d_out, int out_size) {
    const float* h   = (const float*)d_in[0];
    const int*   src = (const int*)d_in[1];
    const int*   dst = (const int*)d_in[2];
    const float* Wq  = (const float*)d_in[3];
    const float* bq  = (const float*)d_in[4];
    const float* Wk  = (const float*)d_in[5];
    const float* bk  = (const float*)d_in[6];
    const float* Wv  = (const float*)d_in[7];
    const float* bv  = (const float*)d_in[8];
    const float* Wo  = (const float*)d_in[9];
    const float* bo  = (const float*)d_in[10];
    float* out = (float*)d_out;

    int n = in_sizes[0] / DIM;
    int E = in_sizes[1];

    cudaFuncSetAttribute(qkv_kernel,
                         cudaFuncAttributeMaxDynamicSharedMemorySize, QKV_SMEM);
    cudaFuncSetAttribute(outproj_kernel,
                         cudaFuncAttributeMaxDynamicSharedMemorySize, OUT_SMEM);

    init_kernel<<<4096, 256>>>(n);
    qkv_kernel<<<148, 768, QKV_SMEM>>>(h, Wq, bq, Wk, bk, Wv, bv, n);

    int eblocks = (E + 7) / 8;                 // 8 warp-edges per 256-thread block
    scores_kernel<<<eblocks, 256>>>(src, dst, E);
    agg_kernel<<<eblocks, 256>>>(src, dst, E);

    norm_kernel<<<4096, 256>>>(n);
    outproj_kernel<<<296, 512, OUT_SMEM>>>(Wo, bo, out, n);
}

// round 4
// speedup vs baseline: 1.2275x; 1.2275x over previous
#include <cuda_runtime.h>
#include <cuda_bf16.h>

// Problem constants (shapes fixed by the dataset)
#define NMAX 50048        // >= 50000, padded
#define EMAX 800000
#define DIM  128
#define NHEADS 8
#define HDIM 16

// ---------------- scratch (device globals; no allocation allowed) -------------
__device__ __nv_bfloat16 g_qb[NMAX * DIM];
__device__ __nv_bfloat16 g_kb[NMAX * DIM];
__device__ float         g_v[NMAX * DIM];
__device__ float         g_agg[NMAX * DIM];
__device__ float         g_denom[NMAX * NHEADS];

// ---------------- K0: init scratch --------------------------------------------
__global__ void init_kernel(int n) {
    int total = n * DIM;
    int nh = n * NHEADS;
    for (int i = blockIdx.x * blockDim.x + threadIdx.x; i < total;
         i += gridDim.x * blockDim.x) {
        g_agg[i] = 0.0f;
        if (i < nh) g_denom[i] = 0.0f;
    }
}

// ---------------- K1: fused QKV projection ------------------------------------
// out[m][i][j] = b_m[j] + sum_d h[i][d] * W_m[j][d],  m in {q,k,v}
// 768 threads = 2 row-groups x 384 column-threads (384 = 3 matrices x 128 cols).
// Weights live in smem in a float4-friendly, bank-conflict-free padded layout.
#define QKV_NT 384
#define QKV_W4STRIDE (QKV_NT + 1)                 // 385 float4s per d4 slab
#define QKV_WFLOATS  (32 * QKV_W4STRIDE * 4)      // 49280 floats
#define QKV_SMEM ((QKV_WFLOATS + 2 * 16 * DIM) * 4)

__global__ __launch_bounds__(768, 1)
void qkv_kernel(const float* __restrict__ h,
                const float* __restrict__ Wq, const float* __restrict__ bq,
                const float* __restrict__ Wk, const float* __restrict__ bk,
                const float* __restrict__ Wv, const float* __restrict__ bv,
                int n) {
    extern __shared__ float smem[];
    float* Wsf = smem;                     // QKV_WFLOATS
    float* hs  = smem + QKV_WFLOATS;       // 2 groups x 16 rows x 128

    int tid = threadIdx.x;

    // Load 3 x 128 x 128 weights, coalesced global reads, conflict-free STS.
    for (int u = tid; u < 3 * DIM * DIM; u += blockDim.x) {
        int m = u >> 14;
        int rem = u & 16383;           // j*128 + d
        int j = rem >> 7;
        int d = rem & 127;
        int t = m * DIM + j;
        const float* wp = (m == 0) ? Wq : (m == 1) ? Wk : Wv;
        Wsf[(d >> 2) * (QKV_W4STRIDE * 4) + t * 4 + (d & 3)] = wp[rem];
    }

    int grp = tid / QKV_NT;            // 0..1
    int t   = tid % QKV_NT;
    int m   = t >> 7;
    int j   = t & 127;
    float bias = (m == 0) ? bq[j] : (m == 1) ? bk[j] : bv[j];
    float* hsg = hs + grp * 16 * DIM;
    __syncthreads();

    const float4* Ws4 = (const float4*)Wsf;

    for (int b0 = blockIdx.x * 32; b0 < n; b0 += gridDim.x * 32) {
        int r0 = b0 + grp * 16;
        int nr = n - r0;
        nr = nr < 0 ? 0 : (nr > 16 ? 16 : nr);

        for (int u = t; u < nr * DIM; u += QKV_NT)
            hsg[u] = h[(size_t)r0 * DIM + u];
        __syncthreads();

        float acc[16];
        #pragma unroll
        for (int r = 0; r < 16; r++) acc[r] = 0.0f;

        const float4* hs4 = (const float4*)hsg;
        #pragma unroll 8
        for (int d4 = 0; d4 < 32; d4++) {
            float4 w4 = Ws4[d4 * QKV_W4STRIDE + t];
            #pragma unroll
            for (int r = 0; r < 16; r++) {
                float4 h4 = hs4[r * 32 + d4];
                acc[r] = fmaf(h4.x, w4.x,
                         fmaf(h4.y, w4.y,
                         fmaf(h4.z, w4.z,
                         fmaf(h4.w, w4.w, acc[r]))));
            }
        }
        __syncthreads();

        if (m == 0) {
            for (int r = 0; r < nr; r++)
                g_qb[(size_t)(r0 + r) * DIM + j] = __float2bfloat16(acc[r] + bias);
        } else if (m == 1) {
            for (int r = 0; r < nr; r++)
                g_kb[(size_t)(r0 + r) * DIM + j] = __float2bfloat16(acc[r] + bias);
        } else {
            for (int r = 0; r < nr; r++)
                g_v[(size_t)(r0 + r) * DIM + j] = acc[r] + bias;
        }
    }
}

// ---------------- K2: fused edge pass -----------------------------------------
// One warp per edge. Lane l covers dims 4l..4l+3; head = l>>2.
// Softmax is shift-invariant and scores are tiny (|s| << 88), so we skip the
// segment-max entirely: w_e = exp(s_e), normalize by the denom sum later.
__global__ void edge_kernel(const int* __restrict__ src,
                            const int* __restrict__ dst, int E) {
    int w = (blockIdx.x * blockDim.x + threadIdx.x) >> 5;
    int l = threadIdx.x & 31;
    if (w >= E) return;
    int s = src[w];
    int d = dst[w];

    // q, k rows in bf16: lane l loads 4 bf16 = 8 bytes
    uint2 qu = ((const uint2*)g_qb)[(size_t)s * 32 + l];
    uint2 ku = ((const uint2*)g_kb)[(size_t)d * 32 + l];
    float2 q01 = __bfloat1622float2(*(const __nv_bfloat162*)&qu.x);
    float2 q23 = __bfloat1622float2(*(const __nv_bfloat162*)&qu.y);
    float2 k01 = __bfloat1622float2(*(const __nv_bfloat162*)&ku.x);
    float2 k23 = __bfloat1622float2(*(const __nv_bfloat162*)&ku.y);

    float p = q01.x * k01.x + q01.y * k01.y + q23.x * k23.x + q23.y * k23.y;
    p += __shfl_xor_sync(0xffffffffu, p, 1);
    p += __shfl_xor_sync(0xffffffffu, p, 2);
    float we = __expf(p * 0.25f);                // scale = 1/sqrt(16)

    float4 v4 = ((const float4*)g_v)[(size_t)s * 32 + l];
    float* dp = &g_agg[(size_t)d * DIM + l * 4];
    asm volatile("red.global.add.v4.f32 [%0], {%1, %2, %3, %4};"
                 :: "l"(dp), "f"(we * v4.x), "f"(we * v4.y),
                    "f"(we * v4.z), "f"(we * v4.w)
                 : "memory");
    if ((l & 3) == 0) {
        float* dn = &g_denom[(size_t)d * NHEADS + (l >> 2)];
        asm volatile("red.global.add.f32 [%0], %1;" :: "l"(dn), "f"(we)
                     : "memory");
    }
}

// ---------------- K3: output projection (normalization fused into load) -------
// out[i][j] = bo[j] + sum_d (agg[i][d]/denom[i][d/16]) * Wo[j][d]
#define OUT_NT 128
#define OUT_W4STRIDE (OUT_NT + 1)                 // 129 float4s per d4 slab
#define OUT_WFLOATS  (32 * OUT_W4STRIDE * 4)      // 16512 floats
#define OUT_SMEM ((OUT_WFLOATS + 4 * 16 * DIM) * 4)

__global__ __launch_bounds__(512, 2)
void outproj_kernel(const float* __restrict__ W, const float* __restrict__ b,
                    float* __restrict__ out, int n) {
    extern __shared__ float smem[];
    float* Wsf = smem;
    float* hs  = smem + OUT_WFLOATS;

    int tid = threadIdx.x;
    for (int u = tid; u < DIM * DIM; u += blockDim.x) {
        int j = u >> 7;
        int d = u & 127;
        Wsf[(d >> 2) * (OUT_W4STRIDE * 4) + j * 4 + (d & 3)] = W[u];
    }

    int grp = tid >> 7;
    int t   = tid & 127;
    float bias = b[t];
    float* hsg = hs + grp * 16 * DIM;
    __syncthreads();

    const float4* Ws4 = (const float4*)Wsf;

    for (int b0 = blockIdx.x * 64; b0 < n; b0 += gridDim.x * 64) {
        int r0 = b0 + grp * 16;
        int nr = n - r0;
        nr = nr < 0 ? 0 : (nr > 16 ? 16 : nr);

        for (int u = t; u < nr * DIM; u += OUT_NT) {
            int r  = u >> 7;
            int hh = (u & 127) >> 4;
            float dn = g_denom[(size_t)(r0 + r) * NHEADS + hh];
            float a  = g_agg[(size_t)r0 * DIM + u];
            hsg[u] = (dn > 0.0f) ? __fdividef(a, dn) : 0.0f;
        }
        __syncthreads();

        float acc[16];
        #pragma unroll
        for (int r = 0; r < 16; r++) acc[r] = 0.0f;

        const float4* hs4 = (const float4*)hsg;
        #pragma unroll 8
        for (int d4 = 0; d4 < 32; d4++) {
            float4 w4 = Ws4[d4 * OUT_W4STRIDE + t];
            #pragma unroll
            for (int r = 0; r < 16; r++) {
                float4 h4 = hs4[r * 32 + d4];
                acc[r] = fmaf(h4.x, w4.x,
                         fmaf(h4.y, w4.y,
                         fmaf(h4.z, w4.z,
                         fmaf(h4.w, w4.w, acc[r]))));
            }
        }
        __syncthreads();

        for (int r = 0; r < nr; r++)
            out[(size_t)(r0 + r) * DIM + t] = acc[r] + bias;
    }
}

// ---------------- launch -------------------------------------------------------
extern "C" void kernel_launch(void* const* d_in, const int* in_sizes, int n_in,
                              void* d_out, int out_size) {
    const float* h   = (const float*)d_in[0];
    const int*   src = (const int*)d_in[1];
    const int*   dst = (const int*)d_in[2];
    const float* Wq  = (const float*)d_in[3];
    const float* bq  = (const float*)d_in[4];
    const float* Wk  = (const float*)d_in[5];
    const float* bk  = (const float*)d_in[6];
    const float* Wv  = (const float*)d_in[7];
    const float* bv  = (const float*)d_in[8];
    const float* Wo  = (const float*)d_in[9];
    const float* bo  = (const float*)d_in[10];
    float* out = (float*)d_out;

    int n = in_sizes[0] / DIM;
    int E = in_sizes[1];

    cudaFuncSetAttribute(qkv_kernel,
                         cudaFuncAttributeMaxDynamicSharedMemorySize, QKV_SMEM);
    cudaFuncSetAttribute(outproj_kernel,
                         cudaFuncAttributeMaxDynamicSharedMemorySize, OUT_SMEM);

    init_kernel<<<4096, 256>>>(n);
    qkv_kernel<<<148, 768, QKV_SMEM>>>(h, Wq, bq, Wk, bk, Wv, bv, n);

    int eblocks = (E + 7) / 8;                 // 8 warp-edges per 256-thread block
    edge_kernel<<<eblocks, 256>>>(src, dst, E);

    outproj_kernel<<<296, 512, OUT_SMEM>>>(Wo, bo, out, n);
}

// round 9
// speedup vs baseline: 2.4952x; 2.0327x over previous
#include <cuda_runtime.h>
#include <cuda_bf16.h>
#include <cstdint>

// Problem constants (shapes fixed by the dataset)
#define NMAX 50048
#define EMAX 800000
#define DIM  128
#define NHEADS 8
#define HDIM 16

// ---------------- scratch (device globals; no allocation allowed) -------------
__device__ __nv_bfloat16 g_qb[NMAX * DIM];
__device__ __nv_bfloat16 g_kb[NMAX * DIM];
__device__ float         g_v[NMAX * DIM];
__device__ float         g_agg[NMAX * DIM];
__device__ float         g_denom[NMAX * NHEADS];
// bf16 weights (hi / lo split for the precision-critical paths)
__device__ __nv_bfloat16 g_Wqh[DIM * DIM];
__device__ __nv_bfloat16 g_Wkh[DIM * DIM];
__device__ __nv_bfloat16 g_Wvh[DIM * DIM];
__device__ __nv_bfloat16 g_Wvl[DIM * DIM];
__device__ __nv_bfloat16 g_Woh[DIM * DIM];
__device__ __nv_bfloat16 g_Wol[DIM * DIM];

// ---------------- helpers ------------------------------------------------------
__device__ __forceinline__ uint32_t smem_u32(const void* p) {
    uint32_t a;
    asm("{ .reg .u64 t; cvta.to.shared.u64 t, %1; cvt.u32.u64 %0, t; }"
        : "=r"(a) : "l"(p));
    return a;
}

// Swizzled byte offset in a [128 rows x 128 bf16] tile.
// Row = 256B (16 chunks of 16B); chunk index XORed with (row & 7):
// ldmatrix over 8 consecutive rows at a fixed logical chunk hits 8 distinct
// chunks -> 32 distinct banks (conflict-free); 16B alignment preserved.
__device__ __forceinline__ uint32_t toff(int r, int k) {
    return (uint32_t)((r << 8) + ((((k >> 3) ^ (r & 7))) << 4) + ((k & 7) << 1));
}

__device__ __forceinline__ void ldsm4(uint32_t addr, uint32_t* r) {
    asm volatile("ldmatrix.sync.aligned.m8n8.x4.shared.b16 {%0,%1,%2,%3}, [%4];"
                 : "=r"(r[0]), "=r"(r[1]), "=r"(r[2]), "=r"(r[3]) : "r"(addr));
}

__device__ __forceinline__ void mma16816(float* c, const uint32_t* a,
                                         const uint32_t* b) {
    asm volatile(
        "mma.sync.aligned.m16n8k16.row.col.f32.bf16.bf16.f32 "
        "{%0,%1,%2,%3}, {%4,%5,%6,%7}, {%8,%9}, {%0,%1,%2,%3};"
        : "+f"(c[0]), "+f"(c[1]), "+f"(c[2]), "+f"(c[3])
        : "r"(a[0]), "r"(a[1]), "r"(a[2]), "r"(a[3]), "r"(b[0]), "r"(b[1]));
}

// split 8 fp32 into bf16 hi + bf16 lo, packed as 8-bf16 uint4s
__device__ __forceinline__ void split8(const float* x, uint4& uh, uint4& ul) {
    __nv_bfloat162* ph = (__nv_bfloat162*)&uh;
    __nv_bfloat162* pl = (__nv_bfloat162*)&ul;
    #pragma unroll
    for (int i = 0; i < 4; i++) {
        __nv_bfloat16 h0 = __float2bfloat16(x[2 * i]);
        __nv_bfloat16 h1 = __float2bfloat16(x[2 * i + 1]);
        ph[i] = __halves2bfloat162(h0, h1);
        pl[i] = __floats2bfloat162_rn(x[2 * i]     - __bfloat162float(h0),
                                      x[2 * i + 1] - __bfloat162float(h1));
    }
}

// 128x128x128 GEMM tile on tensor cores.
// Passes: acc += Ahi*Bhi + Alo*Bhi (+ Ahi*Blo if BLO).
// Warp tile 32x32: acc[mi(2)][nt(4)][4].
template <bool BLO>
__device__ __forceinline__ void gemm128(uint32_t sb, int a_hi, int a_lo,
                                        int b_hi, int b_lo,
                                        float acc[2][4][4],
                                        int wm, int wn, int lane) {
    int a_row = (lane & 7) + ((lane >> 3) & 1) * 8;
    int a_k   = ((lane >> 4) & 1) * 8;
    int b_row = ((lane >> 4) & 1) * 8 + (lane & 7);
    int b_k   = ((lane >> 3) & 1) * 8;

    #pragma unroll 1
    for (int k0 = 0; k0 < 8; k0++) {
        int kb = k0 * 16;
        uint32_t ah[2][4], al[2][4];
        #pragma unroll
        for (int mi = 0; mi < 2; mi++) {
            int row = wm * 32 + mi * 16 + a_row;
            ldsm4(sb + a_hi + toff(row, kb + a_k), ah[mi]);
            ldsm4(sb + a_lo + toff(row, kb + a_k), al[mi]);
        }
        uint32_t bh[2][4], bl[2][4];
        #pragma unroll
        for (int pr = 0; pr < 2; pr++) {
            int row = wn * 32 + pr * 16 + b_row;
            ldsm4(sb + b_hi + toff(row, kb + b_k), bh[pr]);
            if (BLO) ldsm4(sb + b_lo + toff(row, kb + b_k), bl[pr]);
        }
        #pragma unroll
        for (int mi = 0; mi < 2; mi++) {
            #pragma unroll
            for (int nt = 0; nt < 4; nt++) {
                uint32_t* b = &bh[nt >> 1][(nt & 1) * 2];
                mma16816(acc[mi][nt], ah[mi], b);
                mma16816(acc[mi][nt], al[mi], b);
                if (BLO) mma16816(acc[mi][nt], ah[mi], &bl[nt >> 1][(nt & 1) * 2]);
            }
        }
    }
}

// ---------------- K0: init scratch --------------------------------------------
__global__ void init_kernel(int n) {
    int total = n * DIM;
    int nh = n * NHEADS;
    for (int i = blockIdx.x * blockDim.x + threadIdx.x; i < total;
         i += gridDim.x * blockDim.x) {
        g_agg[i] = 0.0f;
        if (i < nh) g_denom[i] = 0.0f;
    }
}

// ---------------- K0b: weight prep (fp32 -> bf16 hi/lo) ------------------------
__global__ void prep_kernel(const float* __restrict__ Wq, const float* __restrict__ Wk,
                            const float* __restrict__ Wv, const float* __restrict__ Wo) {
    int i = blockIdx.x * blockDim.x + threadIdx.x;
    if (i < DIM * DIM) {
        g_Wqh[i] = __float2bfloat16(Wq[i]);
        g_Wkh[i] = __float2bfloat16(Wk[i]);
        float v = Wv[i];
        __nv_bfloat16 vh = __float2bfloat16(v);
        g_Wvh[i] = vh;
        g_Wvl[i] = __float2bfloat16(v - __bfloat162float(vh));
        float o = Wo[i];
        __nv_bfloat16 oh = __float2bfloat16(o);
        g_Woh[i] = oh;
        g_Wol[i] = __float2bfloat16(o - __bfloat162float(oh));
    }
}

// ---------------- K1: QKV projection via mma.sync bf16 -------------------------
// SMEM: bias(1536B pad to 2048) | Ahi | Alo | Wq | Wk | Wvh | Wvl  (32KB each)
#define QS_AHI  2048
#define QS_ALO  (QS_AHI + 32768)
#define QS_WQ   (QS_ALO + 32768)
#define QS_WK   (QS_WQ + 32768)
#define QS_WVH  (QS_WK + 32768)
#define QS_WVL  (QS_WVH + 32768)
#define QS_TOTAL (QS_WVL + 32768)          // 198656 bytes

__global__ __launch_bounds__(512, 1)
void qkv_mma_kernel(const float* __restrict__ h,
                    const float* __restrict__ bq, const float* __restrict__ bk,
                    const float* __restrict__ bv, int n, int ntiles) {
    extern __shared__ char smem[];
    uint32_t sb = smem_u32(smem);
    int tid = threadIdx.x, wid = tid >> 5, lane = tid & 31;
    int wm = wid & 3, wn = wid >> 2;
    int g = lane >> 2, t = lane & 3;

    float* bias_s = (float*)smem;
    for (int i = tid; i < 384; i += 512)
        bias_s[i] = (i < 128) ? bq[i] : (i < 256) ? bk[i - 128] : bv[i - 256];

    // Stage weights (bf16, swizzled) once
    for (int c = tid; c < 2048; c += 512) {
        int r = c >> 4, k8 = (c & 15) << 3;
        uint32_t off = toff(r, k8);
        int gi = (r * DIM + k8) >> 3;
        *(uint4*)(smem + QS_WQ  + off) = ((const uint4*)g_Wqh)[gi];
        *(uint4*)(smem + QS_WK  + off) = ((const uint4*)g_Wkh)[gi];
        *(uint4*)(smem + QS_WVH + off) = ((const uint4*)g_Wvh)[gi];
        *(uint4*)(smem + QS_WVL + off) = ((const uint4*)g_Wvl)[gi];
    }
    __syncthreads();

    for (int tile = blockIdx.x; tile < ntiles; tile += gridDim.x) {
        int r0 = tile << 7;

        // Stage + split A (h tile)
        for (int c = tid; c < 2048; c += 512) {
            int r = c >> 4, k8 = (c & 15) << 3;
            int gr = r0 + r;
            float x[8] = {0, 0, 0, 0, 0, 0, 0, 0};
            if (gr < n) {
                const float4* hp = (const float4*)(h + (size_t)gr * DIM + k8);
                *(float4*)&x[0] = hp[0];
                *(float4*)&x[4] = hp[1];
            }
            uint4 uh, ul;
            split8(x, uh, ul);
            uint32_t off = toff(r, k8);
            *(uint4*)(smem + QS_AHI + off) = uh;
            *(uint4*)(smem + QS_ALO + off) = ul;
        }
        __syncthreads();

        // ---- q ----
        {
            float acc[2][4][4] = {};
            gemm128<false>(sb, QS_AHI, QS_ALO, QS_WQ, 0, acc, wm, wn, lane);
            #pragma unroll
            for (int mi = 0; mi < 2; mi++) {
                #pragma unroll
                for (int nt = 0; nt < 4; nt++) {
                    int col = wn * 32 + nt * 8 + 2 * t;
                    float b0 = bias_s[col], b1 = bias_s[col + 1];
                    int row = r0 + wm * 32 + mi * 16 + g;
                    if (row < n)
                        *(__nv_bfloat162*)(g_qb + (size_t)row * DIM + col) =
                            __floats2bfloat162_rn(acc[mi][nt][0] + b0,
                                                  acc[mi][nt][1] + b1);
                    if (row + 8 < n)
                        *(__nv_bfloat162*)(g_qb + (size_t)(row + 8) * DIM + col) =
                            __floats2bfloat162_rn(acc[mi][nt][2] + b0,
                                                  acc[mi][nt][3] + b1);
                }
            }
        }
        // ---- k ----
        {
            float acc[2][4][4] = {};
            gemm128<false>(sb, QS_AHI, QS_ALO, QS_WK, 0, acc, wm, wn, lane);
            #pragma unroll
            for (int mi = 0; mi < 2; mi++) {
                #pragma unroll
                for (int nt = 0; nt < 4; nt++) {
                    int col = wn * 32 + nt * 8 + 2 * t;
                    float b0 = bias_s[128 + col], b1 = bias_s[128 + col + 1];
                    int row = r0 + wm * 32 + mi * 16 + g;
                    if (row < n)
                        *(__nv_bfloat162*)(g_kb + (size_t)row * DIM + col) =
                            __floats2bfloat162_rn(acc[mi][nt][0] + b0,
                                                  acc[mi][nt][1] + b1);
                    if (row + 8 < n)
                        *(__nv_bfloat162*)(g_kb + (size_t)(row + 8) * DIM + col) =
                            __floats2bfloat162_rn(acc[mi][nt][2] + b0,
                                                  acc[mi][nt][3] + b1);
                }
            }
        }
        // ---- v (3-pass split) ----
        {
            float acc[2][4][4] = {};
            gemm128<true>(sb, QS_AHI, QS_ALO, QS_WVH, QS_WVL, acc, wm, wn, lane);
            #pragma unroll
            for (int mi = 0; mi < 2; mi++) {
                #pragma unroll
                for (int nt = 0; nt < 4; nt++) {
                    int col = wn * 32 + nt * 8 + 2 * t;
                    float b0 = bias_s[256 + col], b1 = bias_s[256 + col + 1];
                    int row = r0 + wm * 32 + mi * 16 + g;
                    if (row < n) {
                        float2 f = {acc[mi][nt][0] + b0, acc[mi][nt][1] + b1};
                        *(float2*)(g_v + (size_t)row * DIM + col) = f;
                    }
                    if (row + 8 < n) {
                        float2 f = {acc[mi][nt][2] + b0, acc[mi][nt][3] + b1};
                        *(float2*)(g_v + (size_t)(row + 8) * DIM + col) = f;
                    }
                }
            }
        }
        __syncthreads();
    }
}

// ---------------- K2: fused edge pass -----------------------------------------
__global__ void edge_kernel(const int* __restrict__ src,
                            const int* __restrict__ dst, int E) {
    int w = (blockIdx.x * blockDim.x + threadIdx.x) >> 5;
    int l = threadIdx.x & 31;
    if (w >= E) return;
    int s = src[w];
    int d = dst[w];

    uint2 qu = ((const uint2*)g_qb)[(size_t)s * 32 + l];
    uint2 ku = ((const uint2*)g_kb)[(size_t)d * 32 + l];
    float2 q01 = __bfloat1622float2(*(const __nv_bfloat162*)&qu.x);
    float2 q23 = __bfloat1622float2(*(const __nv_bfloat162*)&qu.y);
    float2 k01 = __bfloat1622float2(*(const __nv_bfloat162*)&ku.x);
    float2 k23 = __bfloat1622float2(*(const __nv_bfloat162*)&ku.y);

    float p = q01.x * k01.x + q01.y * k01.y + q23.x * k23.x + q23.y * k23.y;
    p += __shfl_xor_sync(0xffffffffu, p, 1);
    p += __shfl_xor_sync(0xffffffffu, p, 2);
    float we = __expf(p * 0.25f);

    float4 v4 = ((const float4*)g_v)[(size_t)s * 32 + l];
    float* dp = &g_agg[(size_t)d * DIM + l * 4];
    asm volatile("red.global.add.v4.f32 [%0], {%1, %2, %3, %4};"
                 :: "l"(dp), "f"(we * v4.x), "f"(we * v4.y),
                    "f"(we * v4.z), "f"(we * v4.w)
                 : "memory");
    if ((l & 3) == 0) {
        float* dn = &g_denom[(size_t)d * NHEADS + (l >> 2)];
        asm volatile("red.global.add.f32 [%0], %1;" :: "l"(dn), "f"(we)
                     : "memory");
    }
}

// ---------------- K3: output projection via mma.sync bf16 ----------------------
#define OS_AHI  2048
#define OS_ALO  (OS_AHI + 32768)
#define OS_WH   (OS_ALO + 32768)
#define OS_WL   (OS_WH + 32768)
#define OS_TOTAL (OS_WL + 32768)           // 133120 bytes

__global__ __launch_bounds__(512, 1)
void outproj_mma_kernel(const float* __restrict__ bo, float* __restrict__ out,
                        int n, int ntiles) {
    extern __shared__ char smem[];
    uint32_t sb = smem_u32(smem);
    int tid = threadIdx.x, wid = tid >> 5, lane = tid & 31;
    int wm = wid & 3, wn = wid >> 2;
    int g = lane >> 2, t = lane & 3;

    float* bias_s = (float*)smem;
    for (int i = tid; i < 128; i += 512) bias_s[i] = bo[i];

    for (int c = tid; c < 2048; c += 512) {
        int r = c >> 4, k8 = (c & 15) << 3;
        uint32_t off = toff(r, k8);
        int gi = (r * DIM + k8) >> 3;
        *(uint4*)(smem + OS_WH + off) = ((const uint4*)g_Woh)[gi];
        *(uint4*)(smem + OS_WL + off) = ((const uint4*)g_Wol)[gi];
    }
    __syncthreads();

    for (int tile = blockIdx.x; tile < ntiles; tile += gridDim.x) {
        int r0 = tile << 7;

        // Stage A = agg/denom, split hi/lo
        for (int c = tid; c < 2048; c += 512) {
            int r = c >> 4, k8 = (c & 15) << 3;
            int gr = r0 + r;
            float x[8] = {0, 0, 0, 0, 0, 0, 0, 0};
            if (gr < n) {
                const float4* ap = (const float4*)(g_agg + (size_t)gr * DIM + k8);
                *(float4*)&x[0] = ap[0];
                *(float4*)&x[4] = ap[1];
                float dn = g_denom[(size_t)gr * NHEADS + (k8 >> 4)];
                float inv = (dn > 0.0f) ? __frcp_rn(dn) : 0.0f;
                #pragma unroll
                for (int i = 0; i < 8; i++) x[i] *= inv;
            }
            uint4 uh, ul;
            split8(x, uh, ul);
            uint32_t off = toff(r, k8);
            *(uint4*)(smem + OS_AHI + off) = uh;
            *(uint4*)(smem + OS_ALO + off) = ul;
        }
        __syncthreads();

        float acc[2][4][4] = {};
        gemm128<true>(sb, OS_AHI, OS_ALO, OS_WH, OS_WL, acc, wm, wn, lane);

        #pragma unroll
        for (int mi = 0; mi < 2; mi++) {
            #pragma unroll
            for (int nt = 0; nt < 4; nt++) {
                int col = wn * 32 + nt * 8 + 2 * t;
                float b0 = bias_s[col], b1 = bias_s[col + 1];
                int row = r0 + wm * 32 + mi * 16 + g;
                if (row < n) {
                    float2 f = {acc[mi][nt][0] + b0, acc[mi][nt][1] + b1};
                    *(float2*)(out + (size_t)row * DIM + col) = f;
                }
                if (row + 8 < n) {
                    float2 f = {acc[mi][nt][2] + b0, acc[mi][nt][3] + b1};
                    *(float2*)(out + (size_t)(row + 8) * DIM + col) = f;
                }
            }
        }
        __syncthreads();
    }
}

// ---------------- launch -------------------------------------------------------
extern "C" void kernel_launch(void* const* d_in, const int* in_sizes, int n_in,
                              void* d_out, int out_size) {
    const float* h   = (const float*)d_in[0];
    const int*   src = (const int*)d_in[1];
    const int*   dst = (const int*)d_in[2];
    const float* Wq  = (const float*)d_in[3];
    const float* bq  = (const float*)d_in[4];
    const float* Wk  = (const float*)d_in[5];
    const float* bk  = (const float*)d_in[6];
    const float* Wv  = (const float*)d_in[7];
    const float* bv  = (const float*)d_in[8];
    const float* Wo  = (const float*)d_in[9];
    const float* bo  = (const float*)d_in[10];
    float* out = (float*)d_out;

    int n = in_sizes[0] / DIM;
    int E = in_sizes[1];
    int ntiles = (n + 127) / 128;

    cudaFuncSetAttribute(qkv_mma_kernel,
                         cudaFuncAttributeMaxDynamicSharedMemorySize, QS_TOTAL);
    cudaFuncSetAttribute(outproj_mma_kernel,
                         cudaFuncAttributeMaxDynamicSharedMemorySize, OS_TOTAL);

    init_kernel<<<4096, 256>>>(n);
    prep_kernel<<<(DIM * DIM + 255) / 256, 256>>>(Wq, Wk, Wv, Wo);

    qkv_mma_kernel<<<148, 512, QS_TOTAL>>>(h, bq, bk, bv, n, ntiles);

    int eblocks = (E + 7) / 8;
    edge_kernel<<<eblocks, 256>>>(src, dst, E);

    outproj_mma_kernel<<<148, 512, OS_TOTAL>>>(bo, out, n, ntiles);
}

// round 11
// speedup vs baseline: 3.3213x; 1.3311x over previous
#include <cuda_runtime.h>
#include <cuda_bf16.h>
#include <cstdint>

// Problem constants (shapes fixed by the dataset)
#define NMAX 50048
#define NPAD 50176                 // 49 * 1024, for the block scan
#define EMAX 800000
#define DIM  128
#define NHEADS 8
#define HDIM 16

// ---------------- scratch (device globals; no allocation allowed) -------------
__device__ __nv_bfloat16 g_qb[NMAX * DIM];
__device__ __nv_bfloat16 g_kb[NMAX * DIM];
__device__ float         g_v[NMAX * DIM];
__device__ float         g_agg[NMAX * DIM];
__device__ float         g_denom[NMAX * NHEADS];
// CSR-by-dst build
__device__ int g_deg[NPAD];
__device__ int g_cnt[NPAD];
__device__ int g_off[NPAD];
__device__ int g_bsum[64];
__device__ int g_esrc[EMAX];
// bf16 weights (hi / lo split for the precision-critical paths)
__device__ __nv_bfloat16 g_Wqh[DIM * DIM];
__device__ __nv_bfloat16 g_Wkh[DIM * DIM];
__device__ __nv_bfloat16 g_Wvh[DIM * DIM];
__device__ __nv_bfloat16 g_Wvl[DIM * DIM];
__device__ __nv_bfloat16 g_Woh[DIM * DIM];
__device__ __nv_bfloat16 g_Wol[DIM * DIM];

// ---------------- helpers ------------------------------------------------------
__device__ __forceinline__ uint32_t smem_u32(const void* p) {
    uint32_t a;
    asm("{ .reg .u64 t; cvta.to.shared.u64 t, %1; cvt.u32.u64 %0, t; }"
        : "=r"(a) : "l"(p));
    return a;
}

// Swizzled byte offset in a [128 rows x 128 bf16] tile (XOR-16B-chunk swizzle).
__device__ __forceinline__ uint32_t toff(int r, int k) {
    return (uint32_t)((r << 8) + ((((k >> 3) ^ (r & 7))) << 4) + ((k & 7) << 1));
}

__device__ __forceinline__ void ldsm4(uint32_t addr, uint32_t* r) {
    asm volatile("ldmatrix.sync.aligned.m8n8.x4.shared.b16 {%0,%1,%2,%3}, [%4];"
                 : "=r"(r[0]), "=r"(r[1]), "=r"(r[2]), "=r"(r[3]) : "r"(addr));
}

__device__ __forceinline__ void mma16816(float* c, const uint32_t* a,
                                         const uint32_t* b) {
    asm volatile(
        "mma.sync.aligned.m16n8k16.row.col.f32.bf16.bf16.f32 "
        "{%0,%1,%2,%3}, {%4,%5,%6,%7}, {%8,%9}, {%0,%1,%2,%3};"
        : "+f"(c[0]), "+f"(c[1]), "+f"(c[2]), "+f"(c[3])
        : "r"(a[0]), "r"(a[1]), "r"(a[2]), "r"(a[3]), "r"(b[0]), "r"(b[1]));
}

__device__ __forceinline__ void split8(const float* x, uint4& uh, uint4& ul) {
    __nv_bfloat162* ph = (__nv_bfloat162*)&uh;
    __nv_bfloat162* pl = (__nv_bfloat162*)&ul;
    #pragma unroll
    for (int i = 0; i < 4; i++) {
        __nv_bfloat16 h0 = __float2bfloat16(x[2 * i]);
        __nv_bfloat16 h1 = __float2bfloat16(x[2 * i + 1]);
        ph[i] = __halves2bfloat162(h0, h1);
        pl[i] = __floats2bfloat162_rn(x[2 * i]     - __bfloat162float(h0),
                                      x[2 * i + 1] - __bfloat162float(h1));
    }
}

// 128x128x128 GEMM tile: acc += Ahi*Bhi + Alo*Bhi (+ Ahi*Blo if BLO).
template <bool BLO>
__device__ __forceinline__ void gemm128(uint32_t sb, int a_hi, int a_lo,
                                        int b_hi, int b_lo,
                                        float acc[2][4][4],
                                        int wm, int wn, int lane) {
    int a_row = (lane & 7) + ((lane >> 3) & 1) * 8;
    int a_k   = ((lane >> 4) & 1) * 8;
    int b_row = ((lane >> 4) & 1) * 8 + (lane & 7);
    int b_k   = ((lane >> 3) & 1) * 8;

    #pragma unroll 1
    for (int k0 = 0; k0 < 8; k0++) {
        int kb = k0 * 16;
        uint32_t ah[2][4], al[2][4];
        #pragma unroll
        for (int mi = 0; mi < 2; mi++) {
            int row = wm * 32 + mi * 16 + a_row;
            ldsm4(sb + a_hi + toff(row, kb + a_k), ah[mi]);
            ldsm4(sb + a_lo + toff(row, kb + a_k), al[mi]);
        }
        uint32_t bh[2][4], bl[2][4];
        #pragma unroll
        for (int pr = 0; pr < 2; pr++) {
            int row = wn * 32 + pr * 16 + b_row;
            ldsm4(sb + b_hi + toff(row, kb + b_k), bh[pr]);
            if (BLO) ldsm4(sb + b_lo + toff(row, kb + b_k), bl[pr]);
        }
        #pragma unroll
        for (int mi = 0; mi < 2; mi++) {
            #pragma unroll
            for (int nt = 0; nt < 4; nt++) {
                uint32_t* b = &bh[nt >> 1][(nt & 1) * 2];
                mma16816(acc[mi][nt], ah[mi], b);
                mma16816(acc[mi][nt], al[mi], b);
                if (BLO) mma16816(acc[mi][nt], ah[mi], &bl[nt >> 1][(nt & 1) * 2]);
            }
        }
    }
}

// ---------------- K0: init (counters only) -------------------------------------
__global__ void init_kernel() {
    int i = blockIdx.x * blockDim.x + threadIdx.x;
    if (i < NPAD) { g_deg[i] = 0; g_cnt[i] = 0; }
}

// ---------------- K0b: weight prep (fp32 -> bf16 hi/lo) ------------------------
__global__ void prep_kernel(const float* __restrict__ Wq, const float* __restrict__ Wk,
                            const float* __restrict__ Wv, const float* __restrict__ Wo) {
    int i = blockIdx.x * blockDim.x + threadIdx.x;
    if (i < DIM * DIM) {
        g_Wqh[i] = __float2bfloat16(Wq[i]);
        g_Wkh[i] = __float2bfloat16(Wk[i]);
        float v = Wv[i];
        __nv_bfloat16 vh = __float2bfloat16(v);
        g_Wvh[i] = vh;
        g_Wvl[i] = __float2bfloat16(v - __bfloat162float(vh));
        float o = Wo[i];
        __nv_bfloat16 oh = __float2bfloat16(o);
        g_Woh[i] = oh;
        g_Wol[i] = __float2bfloat16(o - __bfloat162float(oh));
    }
}

// ---------------- CSR build: histogram, scan, scatter --------------------------
__global__ void hist_kernel(const int* __restrict__ dst, int E) {
    int e = blockIdx.x * blockDim.x + threadIdx.x;
    if (e < E) atomicAdd(&g_deg[dst[e]], 1);
}

__global__ void scanA_kernel() {               // 49 blocks x 1024
    __shared__ int sh[1024];
    int t = threadIdx.x;
    int i = blockIdx.x * 1024 + t;
    int v = g_deg[i];
    sh[t] = v;
    __syncthreads();
    for (int ofs = 1; ofs < 1024; ofs <<= 1) {
        int x = 0;
        if (t >= ofs) x = sh[t - ofs];
        __syncthreads();
        if (t >= ofs) sh[t] += x;
        __syncthreads();
    }
    g_off[i] = sh[t] - v;                      // exclusive within block
    if (t == 1023) g_bsum[blockIdx.x] = sh[t];
}

__global__ void scanB_kernel() {               // 1 block x 64
    __shared__ int sh[64];
    int t = threadIdx.x;
    int v = (t < 49) ? g_bsum[t] : 0;
    sh[t] = v;
    __syncthreads();
    for (int ofs = 1; ofs < 64; ofs <<= 1) {
        int x = 0;
        if (t >= ofs) x = sh[t - ofs];
        __syncthreads();
        if (t >= ofs) sh[t] += x;
        __syncthreads();
    }
    if (t < 49) g_bsum[t] = sh[t] - v;         // exclusive block offsets
}

__global__ void scanC_kernel() {               // 49 blocks x 1024
    int i = blockIdx.x * 1024 + threadIdx.x;
    g_off[i] += g_bsum[blockIdx.x];
}

__global__ void scatter_kernel(const int* __restrict__ src,
                               const int* __restrict__ dst, int E) {
    int e = blockIdx.x * blockDim.x + threadIdx.x;
    if (e < E) {
        int d = dst[e];
        int pos = g_off[d] + atomicAdd(&g_cnt[d], 1);
        g_esrc[pos] = src[e];
    }
}

// ---------------- K1: QKV projection via mma.sync bf16 -------------------------
#define QS_AHI  2048
#define QS_ALO  (QS_AHI + 32768)
#define QS_WQ   (QS_ALO + 32768)
#define QS_WK   (QS_WQ + 32768)
#define QS_WVH  (QS_WK + 32768)
#define QS_WVL  (QS_WVH + 32768)
#define QS_TOTAL (QS_WVL + 32768)          // 198656 bytes

__global__ __launch_bounds__(512, 1)
void qkv_mma_kernel(const float* __restrict__ h,
                    const float* __restrict__ bq, const float* __restrict__ bk,
                    const float* __restrict__ bv, int n, int ntiles) {
    extern __shared__ char smem[];
    uint32_t sb = smem_u32(smem);
    int tid = threadIdx.x, wid = tid >> 5, lane = tid & 31;
    int wm = wid & 3, wn = wid >> 2;
    int g = lane >> 2, t = lane & 3;

    float* bias_s = (float*)smem;
    for (int i = tid; i < 384; i += 512)
        bias_s[i] = (i < 128) ? bq[i] : (i < 256) ? bk[i - 128] : bv[i - 256];

    for (int c = tid; c < 2048; c += 512) {
        int r = c >> 4, k8 = (c & 15) << 3;
        uint32_t off = toff(r, k8);
        int gi = (r * DIM + k8) >> 3;
        *(uint4*)(smem + QS_WQ  + off) = ((const uint4*)g_Wqh)[gi];
        *(uint4*)(smem + QS_WK  + off) = ((const uint4*)g_Wkh)[gi];
        *(uint4*)(smem + QS_WVH + off) = ((const uint4*)g_Wvh)[gi];
        *(uint4*)(smem + QS_WVL + off) = ((const uint4*)g_Wvl)[gi];
    }
    __syncthreads();

    for (int tile = blockIdx.x; tile < ntiles; tile += gridDim.x) {
        int r0 = tile << 7;

        for (int c = tid; c < 2048; c += 512) {
            int r = c >> 4, k8 = (c & 15) << 3;
            int gr = r0 + r;
            float x[8] = {0, 0, 0, 0, 0, 0, 0, 0};
            if (gr < n) {
                const float4* hp = (const float4*)(h + (size_t)gr * DIM + k8);
                *(float4*)&x[0] = hp[0];
                *(float4*)&x[4] = hp[1];
            }
            uint4 uh, ul;
            split8(x, uh, ul);
            uint32_t off = toff(r, k8);
            *(uint4*)(smem + QS_AHI + off) = uh;
            *(uint4*)(smem + QS_ALO + off) = ul;
        }
        __syncthreads();

        // ---- q ----
        {
            float acc[2][4][4] = {};
            gemm128<false>(sb, QS_AHI, QS_ALO, QS_WQ, 0, acc, wm, wn, lane);
            #pragma unroll
            for (int mi = 0; mi < 2; mi++) {
                #pragma unroll
                for (int nt = 0; nt < 4; nt++) {
                    int col = wn * 32 + nt * 8 + 2 * t;
                    float b0 = bias_s[col], b1 = bias_s[col + 1];
                    int row = r0 + wm * 32 + mi * 16 + g;
                    if (row < n)
                        *(__nv_bfloat162*)(g_qb + (size_t)row * DIM + col) =
                            __floats2bfloat162_rn(acc[mi][nt][0] + b0,
                                                  acc[mi][nt][1] + b1);
                    if (row + 8 < n)
                        *(__nv_bfloat162*)(g_qb + (size_t)(row + 8) * DIM + col) =
                            __floats2bfloat162_rn(acc[mi][nt][2] + b0,
                                                  acc[mi][nt][3] + b1);
                }
            }
        }
        // ---- k ----
        {
            float acc[2][4][4] = {};
            gemm128<false>(sb, QS_AHI, QS_ALO, QS_WK, 0, acc, wm, wn, lane);
            #pragma unroll
            for (int mi = 0; mi < 2; mi++) {
                #pragma unroll
                for (int nt = 0; nt < 4; nt++) {
                    int col = wn * 32 + nt * 8 + 2 * t;
                    float b0 = bias_s[128 + col], b1 = bias_s[128 + col + 1];
                    int row = r0 + wm * 32 + mi * 16 + g;
                    if (row < n)
                        *(__nv_bfloat162*)(g_kb + (size_t)row * DIM + col) =
                            __floats2bfloat162_rn(acc[mi][nt][0] + b0,
                                                  acc[mi][nt][1] + b1);
                    if (row + 8 < n)
                        *(__nv_bfloat162*)(g_kb + (size_t)(row + 8) * DIM + col) =
                            __floats2bfloat162_rn(acc[mi][nt][2] + b0,
                                                  acc[mi][nt][3] + b1);
                }
            }
        }
        // ---- v (3-pass split) ----
        {
            float acc[2][4][4] = {};
            gemm128<true>(sb, QS_AHI, QS_ALO, QS_WVH, QS_WVL, acc, wm, wn, lane);
            #pragma unroll
            for (int mi = 0; mi < 2; mi++) {
                #pragma unroll
                for (int nt = 0; nt < 4; nt++) {
                    int col = wn * 32 + nt * 8 + 2 * t;
                    float b0 = bias_s[256 + col], b1 = bias_s[256 + col + 1];
                    int row = r0 + wm * 32 + mi * 16 + g;
                    if (row < n) {
                        float2 f = {acc[mi][nt][0] + b0, acc[mi][nt][1] + b1};
                        *(float2*)(g_v + (size_t)row * DIM + col) = f;
                    }
                    if (row + 8 < n) {
                        float2 f = {acc[mi][nt][2] + b0, acc[mi][nt][3] + b1};
                        *(float2*)(g_v + (size_t)(row + 8) * DIM + col) = f;
                    }
                }
            }
        }
        __syncthreads();
    }
}

// ---------------- K2: gather pass (one warp per dst node) ----------------------
// acc/denom in registers; agg + denom written ONCE per node (no atomics).
__global__ __launch_bounds__(256)
void gather_kernel(int n) {
    int node = (blockIdx.x * blockDim.x + threadIdx.x) >> 5;
    int l = threadIdx.x & 31;
    if (node >= n) return;

    int beg = g_off[node];
    int end = beg + g_deg[node];

    // k[dst] once per node
    uint2 ku = ((const uint2*)g_kb)[(size_t)node * 32 + l];
    float2 k01 = __bfloat1622float2(*(const __nv_bfloat162*)&ku.x);
    float2 k23 = __bfloat1622float2(*(const __nv_bfloat162*)&ku.y);

    float a0 = 0.f, a1 = 0.f, a2 = 0.f, a3 = 0.f;
    float dsum = 0.f;

    for (int base = beg; base < end; base += 32) {
        int m = end - base;
        if (m > 32) m = 32;
        int sl = (base + l < end) ? g_esrc[base + l] : 0;
        for (int j = 0; j < m; j++) {
            int s = __shfl_sync(0xffffffffu, sl, j);
            uint2 qu = ((const uint2*)g_qb)[(size_t)s * 32 + l];
            float4 v4 = ((const float4*)g_v)[(size_t)s * 32 + l];
            float2 q01 = __bfloat1622float2(*(const __nv_bfloat162*)&qu.x);
            float2 q23 = __bfloat1622float2(*(const __nv_bfloat162*)&qu.y);
            float p = q01.x * k01.x + q01.y * k01.y +
                      q23.x * k23.x + q23.y * k23.y;
            p += __shfl_xor_sync(0xffffffffu, p, 1);
            p += __shfl_xor_sync(0xffffffffu, p, 2);
            float we = __expf(p * 0.25f);
            a0 = fmaf(we, v4.x, a0);
            a1 = fmaf(we, v4.y, a1);
            a2 = fmaf(we, v4.z, a2);
            a3 = fmaf(we, v4.w, a3);
            dsum += we;
        }
    }

    float4 o = {a0, a1, a2, a3};
    ((float4*)g_agg)[(size_t)node * 32 + l] = o;
    if ((l & 3) == 0)
        g_denom[(size_t)node * NHEADS + (l >> 2)] = dsum;
}

// ---------------- K3: output projection via mma.sync bf16 ----------------------
#define OS_AHI  2048
#define OS_ALO  (OS_AHI + 32768)
#define OS_WH   (OS_ALO + 32768)
#define OS_WL   (OS_WH + 32768)
#define OS_TOTAL (OS_WL + 32768)           // 133120 bytes

__global__ __launch_bounds__(512, 1)
void outproj_mma_kernel(const float* __restrict__ bo, float* __restrict__ out,
                        int n, int ntiles) {
    extern __shared__ char smem[];
    uint32_t sb = smem_u32(smem);
    int tid = threadIdx.x, wid = tid >> 5, lane = tid & 31;
    int wm = wid & 3, wn = wid >> 2;
    int g = lane >> 2, t = lane & 3;

    float* bias_s = (float*)smem;
    for (int i = tid; i < 128; i += 512) bias_s[i] = bo[i];

    for (int c = tid; c < 2048; c += 512) {
        int r = c >> 4, k8 = (c & 15) << 3;
        uint32_t off = toff(r, k8);
        int gi = (r * DIM + k8) >> 3;
        *(uint4*)(smem + OS_WH + off) = ((const uint4*)g_Woh)[gi];
        *(uint4*)(smem + OS_WL + off) = ((const uint4*)g_Wol)[gi];
    }
    __syncthreads();

    for (int tile = blockIdx.x; tile < ntiles; tile += gridDim.x) {
        int r0 = tile << 7;

        for (int c = tid; c < 2048; c += 512) {
            int r = c >> 4, k8 = (c & 15) << 3;
            int gr = r0 + r;
            float x[8] = {0, 0, 0, 0, 0, 0, 0, 0};
            if (gr < n) {
                const float4* ap = (const float4*)(g_agg + (size_t)gr * DIM + k8);
                *(float4*)&x[0] = ap[0];
                *(float4*)&x[4] = ap[1];
                float dn = g_denom[(size_t)gr * NHEADS + (k8 >> 4)];
                float inv = (dn > 0.0f) ? __frcp_rn(dn) : 0.0f;
                #pragma unroll
                for (int i = 0; i < 8; i++) x[i] *= inv;
            }
            uint4 uh, ul;
            split8(x, uh, ul);
            uint32_t off = toff(r, k8);
            *(uint4*)(smem + OS_AHI + off) = uh;
            *(uint4*)(smem + OS_ALO + off) = ul;
        }
        __syncthreads();

        float acc[2][4][4] = {};
        gemm128<true>(sb, OS_AHI, OS_ALO, OS_WH, OS_WL, acc, wm, wn, lane);

        #pragma unroll
        for (int mi = 0; mi < 2; mi++) {
            #pragma unroll
            for (int nt = 0; nt < 4; nt++) {
                int col = wn * 32 + nt * 8 + 2 * t;
                float b0 = bias_s[col], b1 = bias_s[col + 1];
                int row = r0 + wm * 32 + mi * 16 + g;
                if (row < n) {
                    float2 f = {acc[mi][nt][0] + b0, acc[mi][nt][1] + b1};
                    *(float2*)(out + (size_t)row * DIM + col) = f;
                }
                if (row + 8 < n) {
                    float2 f = {acc[mi][nt][2] + b0, acc[mi][nt][3] + b1};
                    *(float2*)(out + (size_t)(row + 8) * DIM + col) = f;
                }
            }
        }
        __syncthreads();
    }
}

// ---------------- launch -------------------------------------------------------
extern "C" void kernel_launch(void* const* d_in, const int* in_sizes, int n_in,
                              void* d_out, int out_size) {
    const float* h   = (const float*)d_in[0];
    const int*   src = (const int*)d_in[1];
    const int*   dst = (const int*)d_in[2];
    const float* Wq  = (const float*)d_in[3];
    const float* bq  = (const float*)d_in[4];
    const float* Wk  = (const float*)d_in[5];
    const float* bk  = (const float*)d_in[6];
    const float* Wv  = (const float*)d_in[7];
    const float* bv  = (const float*)d_in[8];
    const float* Wo  = (const float*)d_in[9];
    const float* bo  = (const float*)d_in[10];
    float* out = (float*)d_out;

    int n = in_sizes[0] / DIM;
    int E = in_sizes[1];
    int ntiles = (n + 127) / 128;

    cudaFuncSetAttribute(qkv_mma_kernel,
                         cudaFuncAttributeMaxDynamicSharedMemorySize, QS_TOTAL);
    cudaFuncSetAttribute(outproj_mma_kernel,
                         cudaFuncAttributeMaxDynamicSharedMemorySize, OS_TOTAL);

    init_kernel<<<(NPAD + 255) / 256, 256>>>();
    prep_kernel<<<(DIM * DIM + 255) / 256, 256>>>(Wq, Wk, Wv, Wo);

    hist_kernel<<<(E + 255) / 256, 256>>>(dst, E);

    qkv_mma_kernel<<<148, 512, QS_TOTAL>>>(h, bq, bk, bv, n, ntiles);

    scanA_kernel<<<NPAD / 1024, 1024>>>();
    scanB_kernel<<<1, 64>>>();
    scanC_kernel<<<NPAD / 1024, 1024>>>();
    scatter_kernel<<<(E + 255) / 256, 256>>>(src, dst, E);

    gather_kernel<<<(n * 32 + 255) / 256, 256>>>(n);

    outproj_mma_kernel<<<148, 512, OS_TOTAL>>>(bo, out, n, ntiles);
}

// round 13
// speedup vs baseline: 3.4915x; 1.0512x over previous
#include <cuda_runtime.h>
#include <cuda_bf16.h>
#include <cuda_fp16.h>
#include <cstdint>

// Problem constants (shapes fixed by the dataset)
#define NMAX 50048
#define NPAD 50176                 // 49 * 1024, for the block scan
#define EMAX 800000
#define DIM  128
#define NHEADS 8
#define HDIM 16

// ---------------- scratch (device globals; no allocation allowed) -------------
__device__ __half  g_qh[NMAX * DIM];
__device__ __half  g_kh[NMAX * DIM];
__device__ __half  g_vh[NMAX * DIM];
__device__ float   g_agg[NMAX * DIM];
__device__ float   g_denom[NMAX * NHEADS];
// CSR-by-dst build
__device__ int g_deg[NPAD];
__device__ int g_cnt[NPAD];
__device__ int g_off[NPAD];
__device__ int g_bsum[64];
__device__ int g_esrc[EMAX];
// bf16 weights (hi / lo split for the precision-critical paths)
__device__ __nv_bfloat16 g_Wqh[DIM * DIM];
__device__ __nv_bfloat16 g_Wkh[DIM * DIM];
__device__ __nv_bfloat16 g_Wvh[DIM * DIM];
__device__ __nv_bfloat16 g_Wvl[DIM * DIM];
__device__ __nv_bfloat16 g_Woh[DIM * DIM];
__device__ __nv_bfloat16 g_Wol[DIM * DIM];

// ---------------- helpers ------------------------------------------------------
__device__ __forceinline__ uint32_t smem_u32(const void* p) {
    uint32_t a;
    asm("{ .reg .u64 t; cvta.to.shared.u64 t, %1; cvt.u32.u64 %0, t; }"
        : "=r"(a) : "l"(p));
    return a;
}

// Swizzled byte offset in a [128 rows x 128 bf16] tile (XOR-16B-chunk swizzle).
__device__ __forceinline__ uint32_t toff(int r, int k) {
    return (uint32_t)((r << 8) + ((((k >> 3) ^ (r & 7))) << 4) + ((k & 7) << 1));
}

__device__ __forceinline__ void ldsm4(uint32_t addr, uint32_t* r) {
    asm volatile("ldmatrix.sync.aligned.m8n8.x4.shared.b16 {%0,%1,%2,%3}, [%4];"
                 : "=r"(r[0]), "=r"(r[1]), "=r"(r[2]), "=r"(r[3]) : "r"(addr));
}

__device__ __forceinline__ void mma16816(float* c, const uint32_t* a,
                                         const uint32_t* b) {
    asm volatile(
        "mma.sync.aligned.m16n8k16.row.col.f32.bf16.bf16.f32 "
        "{%0,%1,%2,%3}, {%4,%5,%6,%7}, {%8,%9}, {%0,%1,%2,%3};"
        : "+f"(c[0]), "+f"(c[1]), "+f"(c[2]), "+f"(c[3])
        : "r"(a[0]), "r"(a[1]), "r"(a[2]), "r"(a[3]), "r"(b[0]), "r"(b[1]));
}

__device__ __forceinline__ void split8(const float* x, uint4& uh, uint4& ul) {
    __nv_bfloat162* ph = (__nv_bfloat162*)&uh;
    __nv_bfloat162* pl = (__nv_bfloat162*)&ul;
    #pragma unroll
    for (int i = 0; i < 4; i++) {
        __nv_bfloat16 h0 = __float2bfloat16(x[2 * i]);
        __nv_bfloat16 h1 = __float2bfloat16(x[2 * i + 1]);
        ph[i] = __halves2bfloat162(h0, h1);
        pl[i] = __floats2bfloat162_rn(x[2 * i]     - __bfloat162float(h0),
                                      x[2 * i + 1] - __bfloat162float(h1));
    }
}

// 128x128x128 GEMM tile: acc += Ahi*Bhi (+ Alo*Bhi if ALO) (+ Ahi*Blo if BLO).
template <bool ALO, bool BLO>
__device__ __forceinline__ void gemm128(uint32_t sb, int a_hi, int a_lo,
                                        int b_hi, int b_lo,
                                        float acc[2][4][4],
                                        int wm, int wn, int lane) {
    int a_row = (lane & 7) + ((lane >> 3) & 1) * 8;
    int a_k   = ((lane >> 4) & 1) * 8;
    int b_row = ((lane >> 4) & 1) * 8 + (lane & 7);
    int b_k   = ((lane >> 3) & 1) * 8;

    #pragma unroll 1
    for (int k0 = 0; k0 < 8; k0++) {
        int kb = k0 * 16;
        uint32_t ah[2][4], al[2][4];
        #pragma unroll
        for (int mi = 0; mi < 2; mi++) {
            int row = wm * 32 + mi * 16 + a_row;
            ldsm4(sb + a_hi + toff(row, kb + a_k), ah[mi]);
            if (ALO) ldsm4(sb + a_lo + toff(row, kb + a_k), al[mi]);
        }
        uint32_t bh[2][4], bl[2][4];
        #pragma unroll
        for (int pr = 0; pr < 2; pr++) {
            int row = wn * 32 + pr * 16 + b_row;
            ldsm4(sb + b_hi + toff(row, kb + b_k), bh[pr]);
            if (BLO) ldsm4(sb + b_lo + toff(row, kb + b_k), bl[pr]);
        }
        #pragma unroll
        for (int mi = 0; mi < 2; mi++) {
            #pragma unroll
            for (int nt = 0; nt < 4; nt++) {
                uint32_t* b = &bh[nt >> 1][(nt & 1) * 2];
                mma16816(acc[mi][nt], ah[mi], b);
                if (ALO) mma16816(acc[mi][nt], al[mi], b);
                if (BLO) mma16816(acc[mi][nt], ah[mi], &bl[nt >> 1][(nt & 1) * 2]);
            }
        }
    }
}

// ---------------- K0: setup (counters + weight prep fused) ---------------------
__global__ void setup_kernel(const float* __restrict__ Wq, const float* __restrict__ Wk,
                             const float* __restrict__ Wv, const float* __restrict__ Wo) {
    int i = blockIdx.x * blockDim.x + threadIdx.x;
    if (i < NPAD) { g_deg[i] = 0; g_cnt[i] = 0; }
    if (i < DIM * DIM) {
        g_Wqh[i] = __float2bfloat16(Wq[i]);
        g_Wkh[i] = __float2bfloat16(Wk[i]);
        float v = Wv[i];
        __nv_bfloat16 vh = __float2bfloat16(v);
        g_Wvh[i] = vh;
        g_Wvl[i] = __float2bfloat16(v - __bfloat162float(vh));
        float o = Wo[i];
        __nv_bfloat16 oh = __float2bfloat16(o);
        g_Woh[i] = oh;
        g_Wol[i] = __float2bfloat16(o - __bfloat162float(oh));
    }
}

// ---------------- CSR build: histogram, scan, scatter --------------------------
__global__ void hist_kernel(const int* __restrict__ dst, int E) {
    int e = blockIdx.x * blockDim.x + threadIdx.x;
    if (e < E) atomicAdd(&g_deg[dst[e]], 1);
}

__global__ void scanA_kernel() {               // 49 blocks x 1024
    __shared__ int sh[1024];
    int t = threadIdx.x;
    int i = blockIdx.x * 1024 + t;
    int v = g_deg[i];
    sh[t] = v;
    __syncthreads();
    for (int ofs = 1; ofs < 1024; ofs <<= 1) {
        int x = 0;
        if (t >= ofs) x = sh[t - ofs];
        __syncthreads();
        if (t >= ofs) sh[t] += x;
        __syncthreads();
    }
    g_off[i] = sh[t] - v;                      // exclusive within block
    if (t == 1023) g_bsum[blockIdx.x] = sh[t];
}

__global__ void scanB_kernel() {               // 1 block x 64
    __shared__ int sh[64];
    int t = threadIdx.x;
    int v = (t < 49) ? g_bsum[t] : 0;
    sh[t] = v;
    __syncthreads();
    for (int ofs = 1; ofs < 64; ofs <<= 1) {
        int x = 0;
        if (t >= ofs) x = sh[t - ofs];
        __syncthreads();
        if (t >= ofs) sh[t] += x;
        __syncthreads();
    }
    if (t < 49) g_bsum[t] = sh[t] - v;         // exclusive block offsets
}

__global__ void scanC_kernel() {               // 49 blocks x 1024
    int i = blockIdx.x * 1024 + threadIdx.x;
    g_off[i] += g_bsum[blockIdx.x];
}

__global__ void scatter_kernel(const int* __restrict__ src,
                               const int* __restrict__ dst, int E) {
    int e = blockIdx.x * blockDim.x + threadIdx.x;
    if (e < E) {
        int d = dst[e];
        int pos = g_off[d] + atomicAdd(&g_cnt[d], 1);
        g_esrc[pos] = src[e];
    }
}

// ---------------- K1: QKV projection via mma.sync bf16 -------------------------
// q,k: 1-pass (Ahi*W). v: 3-pass split. Next A-tile prefetched into registers.
#define QS_AHI  2048
#define QS_ALO  (QS_AHI + 32768)
#define QS_WQ   (QS_ALO + 32768)
#define QS_WK   (QS_WQ + 32768)
#define QS_WVH  (QS_WK + 32768)
#define QS_WVL  (QS_WVH + 32768)
#define QS_TOTAL (QS_WVL + 32768)          // 198656 bytes

__global__ __launch_bounds__(512, 1)
void qkv_mma_kernel(const float* __restrict__ h,
                    const float* __restrict__ bq, const float* __restrict__ bk,
                    const float* __restrict__ bv, int n, int ntiles) {
    extern __shared__ char smem[];
    uint32_t sb = smem_u32(smem);
    int tid = threadIdx.x, wid = tid >> 5, lane = tid & 31;
    int wm = wid & 3, wn = wid >> 2;
    int g = lane >> 2, t = lane & 3;

    float* bias_s = (float*)smem;
    for (int i = tid; i < 384; i += 512)
        bias_s[i] = (i < 128) ? bq[i] : (i < 256) ? bk[i - 128] : bv[i - 256];

    for (int c = tid; c < 2048; c += 512) {
        int r = c >> 4, k8 = (c & 15) << 3;
        uint32_t off = toff(r, k8);
        int gi = (r * DIM + k8) >> 3;
        *(uint4*)(smem + QS_WQ  + off) = ((const uint4*)g_Wqh)[gi];
        *(uint4*)(smem + QS_WK  + off) = ((const uint4*)g_Wkh)[gi];
        *(uint4*)(smem + QS_WVH + off) = ((const uint4*)g_Wvh)[gi];
        *(uint4*)(smem + QS_WVL + off) = ((const uint4*)g_Wvl)[gi];
    }

    float xr[4][8];
    auto load_tile = [&](int tt) {
        int r0n = tt << 7;
        #pragma unroll
        for (int i = 0; i < 4; i++) {
            int c = tid + (i << 9);
            int r = c >> 4, k8 = (c & 15) << 3;
            int gr = r0n + r;
            if (gr < n) {
                float4 f0 = __ldg((const float4*)(h + (size_t)gr * DIM + k8));
                float4 f1 = __ldg((const float4*)(h + (size_t)gr * DIM + k8 + 4));
                xr[i][0] = f0.x; xr[i][1] = f0.y; xr[i][2] = f0.z; xr[i][3] = f0.w;
                xr[i][4] = f1.x; xr[i][5] = f1.y; xr[i][6] = f1.z; xr[i][7] = f1.w;
            } else {
                #pragma unroll
                for (int j = 0; j < 8; j++) xr[i][j] = 0.0f;
            }
        }
    };
    if (blockIdx.x < ntiles) load_tile(blockIdx.x);
    __syncthreads();

    for (int tile = blockIdx.x; tile < ntiles; tile += gridDim.x) {
        int r0 = tile << 7;

        #pragma unroll
        for (int i = 0; i < 4; i++) {
            int c = tid + (i << 9);
            int r = c >> 4, k8 = (c & 15) << 3;
            uint4 uh, ul;
            split8(xr[i], uh, ul);
            uint32_t off = toff(r, k8);
            *(uint4*)(smem + QS_AHI + off) = uh;
            *(uint4*)(smem + QS_ALO + off) = ul;
        }
        __syncthreads();

        int tn = tile + gridDim.x;
        if (tn < ntiles) load_tile(tn);        // hides under the GEMMs below

        // ---- q (1 pass) ----
        {
            float acc[2][4][4] = {};
            gemm128<false, false>(sb, QS_AHI, QS_ALO, QS_WQ, 0, acc, wm, wn, lane);
            #pragma unroll
            for (int mi = 0; mi < 2; mi++) {
                #pragma unroll
                for (int nt = 0; nt < 4; nt++) {
                    int col = wn * 32 + nt * 8 + 2 * t;
                    float b0 = bias_s[col], b1 = bias_s[col + 1];
                    int row = r0 + wm * 32 + mi * 16 + g;
                    if (row < n)
                        *(__half2*)(g_qh + (size_t)row * DIM + col) =
                            __floats2half2_rn(acc[mi][nt][0] + b0, acc[mi][nt][1] + b1);
                    if (row + 8 < n)
                        *(__half2*)(g_qh + (size_t)(row + 8) * DIM + col) =
                            __floats2half2_rn(acc[mi][nt][2] + b0, acc[mi][nt][3] + b1);
                }
            }
        }
        // ---- k (1 pass) ----
        {
            float acc[2][4][4] = {};
            gemm128<false, false>(sb, QS_AHI, QS_ALO, QS_WK, 0, acc, wm, wn, lane);
            #pragma unroll
            for (int mi = 0; mi < 2; mi++) {
                #pragma unroll
                for (int nt = 0; nt < 4; nt++) {
                    int col = wn * 32 + nt * 8 + 2 * t;
                    float b0 = bias_s[128 + col], b1 = bias_s[128 + col + 1];
                    int row = r0 + wm * 32 + mi * 16 + g;
                    if (row < n)
                        *(__half2*)(g_kh + (size_t)row * DIM + col) =
                            __floats2half2_rn(acc[mi][nt][0] + b0, acc[mi][nt][1] + b1);
                    if (row + 8 < n)
                        *(__half2*)(g_kh + (size_t)(row + 8) * DIM + col) =
                            __floats2half2_rn(acc[mi][nt][2] + b0, acc[mi][nt][3] + b1);
                }
            }
        }
        // ---- v (3-pass split) ----
        {
            float acc[2][4][4] = {};
            gemm128<true, true>(sb, QS_AHI, QS_ALO, QS_WVH, QS_WVL, acc, wm, wn, lane);
            #pragma unroll
            for (int mi = 0; mi < 2; mi++) {
                #pragma unroll
                for (int nt = 0; nt < 4; nt++) {
                    int col = wn * 32 + nt * 8 + 2 * t;
                    float b0 = bias_s[256 + col], b1 = bias_s[256 + col + 1];
                    int row = r0 + wm * 32 + mi * 16 + g;
                    if (row < n)
                        *(__half2*)(g_vh + (size_t)row * DIM + col) =
                            __floats2half2_rn(acc[mi][nt][0] + b0, acc[mi][nt][1] + b1);
                    if (row + 8 < n)
                        *(__half2*)(g_vh + (size_t)(row + 8) * DIM + col) =
                            __floats2half2_rn(acc[mi][nt][2] + b0, acc[mi][nt][3] + b1);
                }
            }
        }
        __syncthreads();
    }
}

// ---------------- K2: gather pass (one warp per dst node) ----------------------
__global__ __launch_bounds__(256)
void gather_kernel(int n) {
    int node = (blockIdx.x * blockDim.x + threadIdx.x) >> 5;
    int l = threadIdx.x & 31;
    if (node >= n) return;

    int beg = g_off[node];
    int end = beg + g_deg[node];

    uint2 ku = __ldg(((const uint2*)g_kh) + (size_t)node * 32 + l);
    float2 k01 = __half22float2(*(const __half2*)&ku.x);
    float2 k23 = __half22float2(*(const __half2*)&ku.y);

    float a0 = 0.f, a1 = 0.f, a2 = 0.f, a3 = 0.f;
    float dsum = 0.f;

    for (int base = beg; base < end; base += 32) {
        int m = end - base;
        if (m > 32) m = 32;
        int sl = (base + l < end) ? __ldg(&g_esrc[base + l]) : 0;
        #pragma unroll 2
        for (int j = 0; j < m; j++) {
            int s = __shfl_sync(0xffffffffu, sl, j);
            uint2 qu = __ldg(((const uint2*)g_qh) + (size_t)s * 32 + l);
            uint2 vu = __ldg(((const uint2*)g_vh) + (size_t)s * 32 + l);
            float2 q01 = __half22float2(*(const __half2*)&qu.x);
            float2 q23 = __half22float2(*(const __half2*)&qu.y);
            float p = q01.x * k01.x + q01.y * k01.y +
                      q23.x * k23.x + q23.y * k23.y;
            p += __shfl_xor_sync(0xffffffffu, p, 1);
            p += __shfl_xor_sync(0xffffffffu, p, 2);
            float we = __expf(p * 0.25f);
            float2 v01 = __half22float2(*(const __half2*)&vu.x);
            float2 v23 = __half22float2(*(const __half2*)&vu.y);
            a0 = fmaf(we, v01.x, a0);
            a1 = fmaf(we, v01.y, a1);
            a2 = fmaf(we, v23.x, a2);
            a3 = fmaf(we, v23.y, a3);
            dsum += we;
        }
    }

    float4 o = {a0, a1, a2, a3};
    ((float4*)g_agg)[(size_t)node * 32 + l] = o;
    if ((l & 3) == 0)
        g_denom[(size_t)node * NHEADS + (l >> 2)] = dsum;
}

// ---------------- K3: output projection via mma.sync bf16 ----------------------
#define OS_AHI  2048
#define OS_ALO  (OS_AHI + 32768)
#define OS_WH   (OS_ALO + 32768)
#define OS_WL   (OS_WH + 32768)
#define OS_TOTAL (OS_WL + 32768)           // 133120 bytes

__global__ __launch_bounds__(512, 1)
void outproj_mma_kernel(const float* __restrict__ bo, float* __restrict__ out,
                        int n, int ntiles) {
    extern __shared__ char smem[];
    uint32_t sb = smem_u32(smem);
    int tid = threadIdx.x, wid = tid >> 5, lane = tid & 31;
    int wm = wid & 3, wn = wid >> 2;
    int g = lane >> 2, t = lane & 3;

    float* bias_s = (float*)smem;
    for (int i = tid; i < 128; i += 512) bias_s[i] = bo[i];

    for (int c = tid; c < 2048; c += 512) {
        int r = c >> 4, k8 = (c & 15) << 3;
        uint32_t off = toff(r, k8);
        int gi = (r * DIM + k8) >> 3;
        *(uint4*)(smem + OS_WH + off) = ((const uint4*)g_Woh)[gi];
        *(uint4*)(smem + OS_WL + off) = ((const uint4*)g_Wol)[gi];
    }

    float xr[4][8];
    float dnr[4];
    auto load_tile = [&](int tt) {
        int r0n = tt << 7;
        #pragma unroll
        for (int i = 0; i < 4; i++) {
            int c = tid + (i << 9);
            int r = c >> 4, k8 = (c & 15) << 3;
            int gr = r0n + r;
            if (gr < n) {
                float4 f0 = __ldg((const float4*)(g_agg + (size_t)gr * DIM + k8));
                float4 f1 = __ldg((const float4*)(g_agg + (size_t)gr * DIM + k8 + 4));
                xr[i][0] = f0.x; xr[i][1] = f0.y; xr[i][2] = f0.z; xr[i][3] = f0.w;
                xr[i][4] = f1.x; xr[i][5] = f1.y; xr[i][6] = f1.z; xr[i][7] = f1.w;
                dnr[i] = __ldg(&g_denom[(size_t)gr * NHEADS + (k8 >> 4)]);
            } else {
                #pragma unroll
                for (int j = 0; j < 8; j++) xr[i][j] = 0.0f;
                dnr[i] = 0.0f;
            }
        }
    };
    if (blockIdx.x < ntiles) load_tile(blockIdx.x);
    __syncthreads();

    for (int tile = blockIdx.x; tile < ntiles; tile += gridDim.x) {
        int r0 = tile << 7;

        #pragma unroll
        for (int i = 0; i < 4; i++) {
            int c = tid + (i << 9);
            int r = c >> 4, k8 = (c & 15) << 3;
            float inv = (dnr[i] > 0.0f) ? __frcp_rn(dnr[i]) : 0.0f;
            float x[8];
            #pragma unroll
            for (int j = 0; j < 8; j++) x[j] = xr[i][j] * inv;
            uint4 uh, ul;
            split8(x, uh, ul);
            uint32_t off = toff(r, k8);
            *(uint4*)(smem + OS_AHI + off) = uh;
            *(uint4*)(smem + OS_ALO + off) = ul;
        }
        __syncthreads();

        int tn = tile + gridDim.x;
        if (tn < ntiles) load_tile(tn);

        float acc[2][4][4] = {};
        gemm128<true, true>(sb, OS_AHI, OS_ALO, OS_WH, OS_WL, acc, wm, wn, lane);

        #pragma unroll
        for (int mi = 0; mi < 2; mi++) {
            #pragma unroll
            for (int nt = 0; nt < 4; nt++) {
                int col = wn * 32 + nt * 8 + 2 * t;
                float b0 = bias_s[col], b1 = bias_s[col + 1];
                int row = r0 + wm * 32 + mi * 16 + g;
                if (row < n) {
                    float2 f = {acc[mi][nt][0] + b0, acc[mi][nt][1] + b1};
                    *(float2*)(out + (size_t)row * DIM + col) = f;
                }
                if (row + 8 < n) {
                    float2 f = {acc[mi][nt][2] + b0, acc[mi][nt][3] + b1};
                    *(float2*)(out + (size_t)(row + 8) * DIM + col) = f;
                }
            }
        }
        __syncthreads();
    }
}

// ---------------- launch -------------------------------------------------------
extern "C" void kernel_launch(void* const* d_in, const int* in_sizes, int n_in,
                              void* d_out, int out_size) {
    const float* h   = (const float*)d_in[0];
    const int*   src = (const int*)d_in[1];
    const int*   dst = (const int*)d_in[2];
    const float* Wq  = (const float*)d_in[3];
    const float* bq  = (const float*)d_in[4];
    const float* Wk  = (const float*)d_in[5];
    const float* bk  = (const float*)d_in[6];
    const float* Wv  = (const float*)d_in[7];
    const float* bv  = (const float*)d_in[8];
    const float* Wo  = (const float*)d_in[9];
    const float* bo  = (const float*)d_in[10];
    float* out = (float*)d_out;

    int n = in_sizes[0] / DIM;
    int E = in_sizes[1];
    int ntiles = (n + 127) / 128;

    cudaFuncSetAttribute(qkv_mma_kernel,
                         cudaFuncAttributeMaxDynamicSharedMemorySize, QS_TOTAL);
    cudaFuncSetAttribute(outproj_mma_kernel,
                         cudaFuncAttributeMaxDynamicSharedMemorySize, OS_TOTAL);

    setup_kernel<<<(NPAD + 255) / 256, 256>>>(Wq, Wk, Wv, Wo);
    hist_kernel<<<(E + 255) / 256, 256>>>(dst, E);

    qkv_mma_kernel<<<148, 512, QS_TOTAL>>>(h, bq, bk, bv, n, ntiles);

    scanA_kernel<<<NPAD / 1024, 1024>>>();
    scanB_kernel<<<1, 64>>>();
    scanC_kernel<<<NPAD / 1024, 1024>>>();
    scatter_kernel<<<(E + 255) / 256, 256>>>(src, dst, E);

    gather_kernel<<<(n * 32 + 255) / 256, 256>>>(n);

    outproj_mma_kernel<<<148, 512, OS_TOTAL>>>(bo, out, n, ntiles);
}